// round 1
// baseline (speedup 1.0000x reference)
#include <cuda_runtime.h>

#define N_TOK 2048
#define B_SZ  8
#define E_DIM 256
#define H_DIM 512

#define BM 128
#define BN 128
#define BK 16
#define TM 8
#define TN 8

// Scratch (static device globals — no runtime allocation).
__device__ float g_xn[(size_t)B_SZ * N_TOK * E_DIM];          // 16 MB, (B,N,E)
__device__ float g_P[(size_t)B_SZ * N_TOK * N_TOK];           // 134 MB, exp(scores)
__device__ float g_rowsum[B_SZ * N_TOK];
__device__ float g_sumsq[1];

// ---------------------------------------------------------------------------
// Kernel 1: row-normalize x (N,B,E) -> g_xn (B,N,E); zero accumulators.
// One warp per row of 256 floats.
// ---------------------------------------------------------------------------
__global__ __launch_bounds__(256) void k_normalize(const float* __restrict__ x) {
    if (blockIdx.x == 0) {
        for (int i = threadIdx.x; i < B_SZ * N_TOK; i += blockDim.x) g_rowsum[i] = 0.f;
        if (threadIdx.x == 0) g_sumsq[0] = 0.f;
    }
    int warp = (blockIdx.x * blockDim.x + threadIdx.x) >> 5;
    int lane = threadIdx.x & 31;
    if (warp >= B_SZ * N_TOK) return;
    int b = warp / N_TOK;
    int i = warp % N_TOK;

    const float4* row = (const float4*)(x + ((size_t)i * B_SZ + b) * E_DIM);
    float4 v0 = row[lane];
    float4 v1 = row[lane + 32];
    float ss = v0.x * v0.x + v0.y * v0.y + v0.z * v0.z + v0.w * v0.w
             + v1.x * v1.x + v1.y * v1.y + v1.z * v1.z + v1.w * v1.w;
#pragma unroll
    for (int o = 16; o; o >>= 1) ss += __shfl_xor_sync(0xffffffffu, ss, o);
    float r = rsqrtf(ss);
    float4* dst = (float4*)(g_xn + ((size_t)b * N_TOK + i) * E_DIM);
    v0.x *= r; v0.y *= r; v0.z *= r; v0.w *= r;
    v1.x *= r; v1.y *= r; v1.z *= r; v1.w *= r;
    dst[lane] = v0;
    dst[lane + 32] = v1;
}

// ---------------------------------------------------------------------------
// Kernel 2: per batch, P = exp(xn @ xn^T) (raw exp == softmax numerator since
// logits are cosines in [-1,1]); fused per-row sums into g_rowsum (atomics).
// Classic 128x128x16 register-tiled SGEMM, 256 threads, 8x8 microtile.
// ---------------------------------------------------------------------------
__global__ __launch_bounds__(256) void k_qk_exp() {
    const int b    = blockIdx.z;
    const int row0 = blockIdx.y * BM;
    const int col0 = blockIdx.x * BN;

    __shared__ float As[BK][BM];
    __shared__ float Bs[BK][BN];

    const float* Xb = g_xn + (size_t)b * N_TOK * E_DIM;
    const int tid = threadIdx.x;
    const int tx = tid & 15;
    const int ty = tid >> 4;

    float acc[TM][TN] = {};

    for (int k0 = 0; k0 < E_DIM; k0 += BK) {
#pragma unroll
        for (int l = 0; l < 2; l++) {
            int idx = tid + l * 256;          // 0..511
            int m   = idx >> 2;               // 0..127
            int kq  = (idx & 3) * 4;          // 0,4,8,12
            float4 va = *(const float4*)(Xb + (size_t)(row0 + m) * E_DIM + k0 + kq);
            As[kq + 0][m] = va.x; As[kq + 1][m] = va.y;
            As[kq + 2][m] = va.z; As[kq + 3][m] = va.w;
            float4 vb = *(const float4*)(Xb + (size_t)(col0 + m) * E_DIM + k0 + kq);
            Bs[kq + 0][m] = vb.x; Bs[kq + 1][m] = vb.y;
            Bs[kq + 2][m] = vb.z; Bs[kq + 3][m] = vb.w;
        }
        __syncthreads();
#pragma unroll
        for (int k = 0; k < BK; k++) {
            float4 a0 = *(const float4*)&As[k][ty * TM];
            float4 a1 = *(const float4*)&As[k][ty * TM + 4];
            float4 b0 = *(const float4*)&Bs[k][tx * TN];
            float4 b1 = *(const float4*)&Bs[k][tx * TN + 4];
            float ar[TM] = {a0.x, a0.y, a0.z, a0.w, a1.x, a1.y, a1.z, a1.w};
            float br[TN] = {b0.x, b0.y, b0.z, b0.w, b1.x, b1.y, b1.z, b1.w};
#pragma unroll
            for (int i = 0; i < TM; i++)
#pragma unroll
                for (int j = 0; j < TN; j++)
                    acc[i][j] = fmaf(ar[i], br[j], acc[i][j]);
        }
        __syncthreads();
    }

    float* Pb = g_P + (size_t)b * N_TOK * N_TOK;
#pragma unroll
    for (int i = 0; i < TM; i++) {
        int gi = row0 + ty * TM + i;
        float e[TN];
        float rs = 0.f;
#pragma unroll
        for (int j = 0; j < TN; j++) {
            e[j] = __expf(acc[i][j]);
            rs += e[j];
        }
        float4* dst = (float4*)(Pb + (size_t)gi * N_TOK + col0 + tx * TN);
        dst[0] = make_float4(e[0], e[1], e[2], e[3]);
        dst[1] = make_float4(e[4], e[5], e[6], e[7]);
        // reduce rs across the 16 threads (tx) sharing this output row;
        // lanes {0..15} and {16..31} hold distinct ty, xor<16 stays in-group.
#pragma unroll
        for (int o = 1; o < 16; o <<= 1) rs += __shfl_xor_sync(0xffffffffu, rs, o);
        if (tx == 0) atomicAdd(&g_rowsum[b * N_TOK + gi], rs);
    }
}

// ---------------------------------------------------------------------------
// Kernel 3: out_unnorm = (P @ h_b) / rowsum   (H factor cancels in final norm)
// Also accumulates global sum of squares into g_sumsq.
// ---------------------------------------------------------------------------
__global__ __launch_bounds__(256) void k_pv(const float* __restrict__ h,
                                            float* __restrict__ out) {
    const int b    = blockIdx.z;
    const int row0 = blockIdx.y * BM;
    const int col0 = blockIdx.x * BN;

    __shared__ float As[BK][BM];
    __shared__ float Bs[BK][BN];

    const float* Pb = g_P + (size_t)b * N_TOK * N_TOK;
    const int tid = threadIdx.x;
    const int tx = tid & 15;
    const int ty = tid >> 4;

    float acc[TM][TN] = {};

    for (int k0 = 0; k0 < N_TOK; k0 += BK) {
#pragma unroll
        for (int l = 0; l < 2; l++) {
            int idx = tid + l * 256;
            {   // A tile: P rows
                int m  = idx >> 2;
                int kq = (idx & 3) * 4;
                float4 va = *(const float4*)(Pb + (size_t)(row0 + m) * N_TOK + k0 + kq);
                As[kq + 0][m] = va.x; As[kq + 1][m] = va.y;
                As[kq + 2][m] = va.z; As[kq + 3][m] = va.w;
            }
            {   // B tile: h[(k0+k), b, col0+nq..]; (N,B,H) layout
                int k  = idx >> 5;
                int nq = (idx & 31) * 4;
                float4 vb = *(const float4*)(h + (size_t)(k0 + k) * (B_SZ * H_DIM)
                                               + b * H_DIM + col0 + nq);
                *(float4*)&Bs[k][nq] = vb;
            }
        }
        __syncthreads();
#pragma unroll
        for (int k = 0; k < BK; k++) {
            float4 a0 = *(const float4*)&As[k][ty * TM];
            float4 a1 = *(const float4*)&As[k][ty * TM + 4];
            float4 b0 = *(const float4*)&Bs[k][tx * TN];
            float4 b1 = *(const float4*)&Bs[k][tx * TN + 4];
            float ar[TM] = {a0.x, a0.y, a0.z, a0.w, a1.x, a1.y, a1.z, a1.w};
            float br[TN] = {b0.x, b0.y, b0.z, b0.w, b1.x, b1.y, b1.z, b1.w};
#pragma unroll
            for (int i = 0; i < TM; i++)
#pragma unroll
                for (int j = 0; j < TN; j++)
                    acc[i][j] = fmaf(ar[i], br[j], acc[i][j]);
        }
        __syncthreads();
    }

    float ssq = 0.f;
#pragma unroll
    for (int i = 0; i < TM; i++) {
        int gi = row0 + ty * TM + i;
        float inv = 1.f / g_rowsum[b * N_TOK + gi];
        float v[TN];
#pragma unroll
        for (int j = 0; j < TN; j++) {
            v[j] = acc[i][j] * inv;
            ssq = fmaf(v[j], v[j], ssq);
        }
        float4* dst = (float4*)(out + ((size_t)gi * B_SZ + b) * H_DIM + col0 + tx * TN);
        dst[0] = make_float4(v[0], v[1], v[2], v[3]);
        dst[1] = make_float4(v[4], v[5], v[6], v[7]);
    }

    __shared__ float red[256];
    red[tid] = ssq;
    __syncthreads();
#pragma unroll
    for (int s = 128; s > 0; s >>= 1) {
        if (tid < s) red[tid] += red[tid + s];
        __syncthreads();
    }
    if (tid == 0) atomicAdd(&g_sumsq[0], red[0]);
}

// ---------------------------------------------------------------------------
// Kernel 4: out *= rsqrt(sum(out^2))
// ---------------------------------------------------------------------------
__global__ void k_scale(float* __restrict__ out) {
    float s = rsqrtf(g_sumsq[0]);
    const int total4 = (N_TOK * B_SZ * H_DIM) / 4;
    float4* o4 = (float4*)out;
    for (int i = blockIdx.x * blockDim.x + threadIdx.x; i < total4;
         i += gridDim.x * blockDim.x) {
        float4 v = o4[i];
        v.x *= s; v.y *= s; v.z *= s; v.w *= s;
        o4[i] = v;
    }
}

extern "C" void kernel_launch(void* const* d_in, const int* in_sizes, int n_in,
                              void* d_out, int out_size) {
    (void)in_sizes; (void)n_in; (void)out_size;
    const float* x = (const float*)d_in[0];
    const float* h = (const float*)d_in[1];
    float* out = (float*)d_out;

    k_normalize<<<(B_SZ * N_TOK) / 8, 256>>>(x);

    dim3 g2(N_TOK / BN, N_TOK / BM, B_SZ);   // 16 x 16 x 8
    k_qk_exp<<<g2, 256>>>();

    dim3 g3(H_DIM / BN, N_TOK / BM, B_SZ);   // 4 x 16 x 8
    k_pv<<<g3, 256>>>(h, out);

    k_scale<<<1024, 256>>>(out);
}

// round 4
// speedup vs baseline: 1.8440x; 1.8440x over previous
#include <cuda_runtime.h>
#include <cuda_bf16.h>
#include <cstdint>

#define N_TOK 2048
#define B_SZ  8
#define E_DIM 256
#define H_DIM 512

// ---------------------------------------------------------------------------
// Scratch (static device globals — no runtime allocation).
// ---------------------------------------------------------------------------
__device__ __nv_bfloat16 g_xh[(size_t)B_SZ * N_TOK * E_DIM];   // xn hi (B,N,E)
__device__ __nv_bfloat16 g_xl[(size_t)B_SZ * N_TOK * E_DIM];   // xn lo
__device__ __nv_bfloat16 g_hth[(size_t)B_SZ * H_DIM * N_TOK];  // h^T hi (B,H,N)
__device__ __nv_bfloat16 g_htl[(size_t)B_SZ * H_DIM * N_TOK];  // h^T lo
__device__ __nv_bfloat16 g_Ph[(size_t)B_SZ * N_TOK * N_TOK];   // exp(scores) hi
__device__ __nv_bfloat16 g_Pl[(size_t)B_SZ * N_TOK * N_TOK];   // exp(scores) lo
__device__ float g_rowsum[B_SZ * N_TOK];
__device__ float g_sumsq[1];

// ---------------------------------------------------------------------------
// Helpers (plain sm_103-compatible PTX: ldmatrix / mma.sync / cp.async)
// ---------------------------------------------------------------------------
__device__ __forceinline__ uint32_t smem_u32(const void* p) {
    uint32_t a;
    asm("{ .reg .u64 t; cvta.to.shared.u64 t, %1; cvt.u32.u64 %0, t; }" : "=r"(a) : "l"(p));
    return a;
}
__device__ __forceinline__ void cpa16(uint32_t dst, const void* src) {
    asm volatile("cp.async.cg.shared.global [%0], [%1], 16;"
                 :: "r"(dst), "l"(__cvta_generic_to_global(src)));
}
#define CP_COMMIT() asm volatile("cp.async.commit_group;" ::: "memory")
#define CP_WAIT(n)  asm volatile("cp.async.wait_group %0;" :: "n"(n) : "memory")

#define LDSM4(r0, r1, r2, r3, addr) \
    asm volatile("ldmatrix.sync.aligned.m8n8.x4.shared.b16 {%0,%1,%2,%3}, [%4];" \
                 : "=r"(r0), "=r"(r1), "=r"(r2), "=r"(r3) : "r"(addr))

#define MMA(c, a, b0, b1) \
    asm volatile("mma.sync.aligned.m16n8k16.row.col.f32.bf16.bf16.f32 " \
                 "{%0,%1,%2,%3},{%4,%5,%6,%7},{%8,%9},{%0,%1,%2,%3};" \
                 : "+f"((c)[0]), "+f"((c)[1]), "+f"((c)[2]), "+f"((c)[3]) \
                 : "r"((a)[0]), "r"((a)[1]), "r"((a)[2]), "r"((a)[3]), "r"(b0), "r"(b1))

// SW128 swizzle: 128-byte rows, xor bits[6:4] ^= bits[9:7]
#define SW(o) ((o) ^ (((o) >> 3) & 0x70u))

__device__ __forceinline__ void split_bf16(float v, __nv_bfloat16& hi, __nv_bfloat16& lo) {
    hi = __float2bfloat16(v);
    lo = __float2bfloat16(v - __bfloat162float(hi));
}

// ---------------------------------------------------------------------------
// Core MMA chunk: BK=64 (4 k16 steps). Tiles are 128-row x 128-byte, SW128.
// Warp tile 32m x 64n. 3 passes: Ah*Bh + Ah*Bl + Al*Bh.
// aRow/bRow: per-lane ldmatrix byte offsets (row*128 + kc*16) within tile.
// ---------------------------------------------------------------------------
__device__ __forceinline__ void mma_chunk(uint32_t ahB, uint32_t alB,
                                          uint32_t bhB, uint32_t blB,
                                          uint32_t aRow, uint32_t bRow,
                                          float acc[2][8][4]) {
#pragma unroll
    for (int k16 = 0; k16 < 4; k16++) {
        uint32_t aoff = SW(aRow + k16 * 32);
        uint32_t boff = SW(bRow + k16 * 32);
        uint32_t ah[2][4], al[2][4], bh[4][4], bl[4][4];
#pragma unroll
        for (int mi = 0; mi < 2; mi++) {
            LDSM4(ah[mi][0], ah[mi][1], ah[mi][2], ah[mi][3], ahB + aoff + mi * 2048);
            LDSM4(al[mi][0], al[mi][1], al[mi][2], al[mi][3], alB + aoff + mi * 2048);
        }
#pragma unroll
        for (int g = 0; g < 4; g++) {
            LDSM4(bh[g][0], bh[g][1], bh[g][2], bh[g][3], bhB + boff + g * 2048);
            LDSM4(bl[g][0], bl[g][1], bl[g][2], bl[g][3], blB + boff + g * 2048);
        }
#pragma unroll
        for (int mi = 0; mi < 2; mi++)
#pragma unroll
            for (int ni = 0; ni < 8; ni++) {
                const int g = ni >> 1, p = (ni & 1) * 2;
                MMA(acc[mi][ni], ah[mi], bh[g][p], bh[g][p + 1]);
                MMA(acc[mi][ni], ah[mi], bl[g][p], bl[g][p + 1]);
                MMA(acc[mi][ni], al[mi], bh[g][p], bh[g][p + 1]);
            }
    }
}

// per-lane ldmatrix row offsets
__device__ __forceinline__ uint32_t a_row_off(int mbase, int lane) {
    int row = mbase + (lane & 7) + ((lane >> 3) & 1) * 8;
    return (uint32_t)(row * 128 + (lane >> 4) * 16);
}
__device__ __forceinline__ uint32_t b_row_off(int nbase, int lane) {
    int row = nbase + (lane & 7) + ((lane >> 4) << 3);
    return (uint32_t)(row * 128 + ((lane >> 3) & 1) * 16);
}

#define GEMM_SMEM (1024 + 2 * 65536)

// ---------------------------------------------------------------------------
// Kernel 1: row-normalize x (N,B,E) -> bf16 hi/lo (B,N,E); zero accumulators.
// ---------------------------------------------------------------------------
__global__ __launch_bounds__(256) void k_normalize(const float* __restrict__ x) {
    if (blockIdx.x == 0) {
        for (int i = threadIdx.x; i < B_SZ * N_TOK; i += blockDim.x) g_rowsum[i] = 0.f;
        if (threadIdx.x == 0) g_sumsq[0] = 0.f;
    }
    int warp = (blockIdx.x * blockDim.x + threadIdx.x) >> 5;
    int lane = threadIdx.x & 31;
    if (warp >= B_SZ * N_TOK) return;
    int b = warp / N_TOK, i = warp % N_TOK;

    const float4* row = (const float4*)(x + ((size_t)i * B_SZ + b) * E_DIM);
    float4 v0 = row[lane], v1 = row[lane + 32];
    float ss = v0.x*v0.x + v0.y*v0.y + v0.z*v0.z + v0.w*v0.w
             + v1.x*v1.x + v1.y*v1.y + v1.z*v1.z + v1.w*v1.w;
#pragma unroll
    for (int o = 16; o; o >>= 1) ss += __shfl_xor_sync(0xffffffffu, ss, o);
    float r = rsqrtf(ss);

    size_t base = ((size_t)b * N_TOK + i) * E_DIM;
    float v[8] = {v0.x*r, v0.y*r, v0.z*r, v0.w*r, v1.x*r, v1.y*r, v1.z*r, v1.w*r};
    __nv_bfloat16 hs[8], ls[8];
#pragma unroll
    for (int k = 0; k < 8; k++) split_bf16(v[k], hs[k], ls[k]);
#pragma unroll
    for (int half = 0; half < 2; half++) {
        int col = half * 128 + lane * 4;
        union { __nv_bfloat16 b4[4]; uint2 u; } uh, ul;
#pragma unroll
        for (int k = 0; k < 4; k++) { uh.b4[k] = hs[half*4+k]; ul.b4[k] = ls[half*4+k]; }
        *(uint2*)(g_xh + base + col) = uh.u;
        *(uint2*)(g_xl + base + col) = ul.u;
    }
}

// ---------------------------------------------------------------------------
// Kernel 1b: transpose h (N,B,H) -> (B,H,N), split to bf16 hi/lo.
// ---------------------------------------------------------------------------
__global__ void k_ht(const float* __restrict__ h) {
    __shared__ float t[32][33];
    int b = blockIdx.z, tok0 = blockIdx.x * 32, hc0 = blockIdx.y * 32;
    int tx = threadIdx.x, ty = threadIdx.y;
#pragma unroll
    for (int k = 0; k < 4; k++)
        t[ty + 8*k][tx] = h[(size_t)(tok0 + ty + 8*k) * (B_SZ*H_DIM) + b*H_DIM + hc0 + tx];
    __syncthreads();
#pragma unroll
    for (int k = 0; k < 4; k++) {
        int r = ty + 8*k;
        float v = t[tx][r];
        __nv_bfloat16 hi, lo; split_bf16(v, hi, lo);
        size_t o = ((size_t)b * H_DIM + hc0 + r) * N_TOK + tok0 + tx;
        g_hth[o] = hi; g_htl[o] = lo;
    }
}

// ---------------------------------------------------------------------------
// Kernel 2: QK. CTA 128x128, P = exp(xn . xn^T) -> bf16 hi/lo, fused rowsums.
// ---------------------------------------------------------------------------
__global__ __launch_bounds__(256, 1) void k_qk() {
    extern __shared__ char smem_raw[];
    uint32_t sb = (smem_u32(smem_raw) + 1023) & ~1023u;
    const int tid = threadIdx.x, lane = tid & 31, w = tid >> 5;
    const int b = blockIdx.z, row0 = blockIdx.y * 128, col0 = blockIdx.x * 128;

    const __nv_bfloat16* Ah = g_xh + ((size_t)b * N_TOK + row0) * E_DIM;
    const __nv_bfloat16* Al = g_xl + ((size_t)b * N_TOK + row0) * E_DIM;
    const __nv_bfloat16* Bh = g_xh + ((size_t)b * N_TOK + col0) * E_DIM;
    const __nv_bfloat16* Bl = g_xl + ((size_t)b * N_TOK + col0) * E_DIM;

    const int mbase = (w & 3) * 32, nbase = (w >> 2) * 64;
    const uint32_t aRow = a_row_off(mbase, lane);
    const uint32_t bRow = b_row_off(nbase, lane);
    float acc[2][8][4] = {};

    auto load = [&](int c) {
        uint32_t base = sb + (c & 1) * 65536;
        int k0 = c * 64;
#pragma unroll
        for (int t = 0; t < 4; t++) {
            int q = tid + t * 256, r = q >> 3, ch = q & 7;
            uint32_t so = SW((uint32_t)(r * 128 + ch * 16));
            size_t go = (size_t)r * E_DIM + k0 + ch * 8;
            cpa16(base + so,        Ah + go);
            cpa16(base + 16384 + so, Al + go);
            cpa16(base + 32768 + so, Bh + go);
            cpa16(base + 49152 + so, Bl + go);
        }
        CP_COMMIT();
    };

    load(0);
#pragma unroll 1
    for (int c = 0; c < 4; c++) {
        if (c < 3) { load(c + 1); CP_WAIT(1); } else { CP_WAIT(0); }
        __syncthreads();
        uint32_t base = sb + (c & 1) * 65536;
        mma_chunk(base, base + 16384, base + 32768, base + 49152, aRow, bRow, acc);
        __syncthreads();
    }

    // Epilogue: exp, rowsum atomics, bf16 split store of P.
    const int tq = lane >> 2, tr = lane & 3;
    __nv_bfloat16* Phb = g_Ph + (size_t)b * N_TOK * N_TOK;
    __nv_bfloat16* Plb = g_Pl + (size_t)b * N_TOK * N_TOK;
#pragma unroll
    for (int mi = 0; mi < 2; mi++)
#pragma unroll
        for (int rh = 0; rh < 2; rh++) {
            int row = row0 + mbase + mi * 16 + rh * 8 + tq;
            float rs = 0.f;
#pragma unroll
            for (int ni = 0; ni < 8; ni++) {
                float e0 = __expf(acc[mi][ni][rh * 2 + 0]);
                float e1 = __expf(acc[mi][ni][rh * 2 + 1]);
                rs += e0 + e1;
                __nv_bfloat16 h0, l0, h1, l1;
                split_bf16(e0, h0, l0);
                split_bf16(e1, h1, l1);
                size_t off = (size_t)row * N_TOK + col0 + nbase + ni * 8 + tr * 2;
                union { __nv_bfloat16 p[2]; uint32_t u; } ph, pl;
                ph.p[0] = h0; ph.p[1] = h1;
                pl.p[0] = l0; pl.p[1] = l1;
                *(uint32_t*)(Phb + off) = ph.u;
                *(uint32_t*)(Plb + off) = pl.u;
            }
            rs += __shfl_xor_sync(0xffffffffu, rs, 1);
            rs += __shfl_xor_sync(0xffffffffu, rs, 2);
            if (tr == 0) atomicAdd(&g_rowsum[b * N_TOK + row], rs);
        }
}

// ---------------------------------------------------------------------------
// Kernel 3: PV. CTA 128x128, out = (P . h^T)/rowsum, global sumsq.
// ---------------------------------------------------------------------------
__global__ __launch_bounds__(256, 1) void k_pv(float* __restrict__ out) {
    extern __shared__ char smem_raw[];
    uint32_t sb = (smem_u32(smem_raw) + 1023) & ~1023u;
    const int tid = threadIdx.x, lane = tid & 31, w = tid >> 5;
    const int b = blockIdx.z, row0 = blockIdx.y * 128, col0 = blockIdx.x * 128;

    const __nv_bfloat16* Ah = g_Ph + ((size_t)b * N_TOK + row0) * N_TOK;
    const __nv_bfloat16* Al = g_Pl + ((size_t)b * N_TOK + row0) * N_TOK;
    const __nv_bfloat16* Bh = g_hth + ((size_t)b * H_DIM + col0) * N_TOK;
    const __nv_bfloat16* Bl = g_htl + ((size_t)b * H_DIM + col0) * N_TOK;

    const int mbase = (w & 3) * 32, nbase = (w >> 2) * 64;
    const uint32_t aRow = a_row_off(mbase, lane);
    const uint32_t bRow = b_row_off(nbase, lane);
    float acc[2][8][4] = {};

    auto load = [&](int c) {
        uint32_t base = sb + (c & 1) * 65536;
        int k0 = c * 64;
#pragma unroll
        for (int t = 0; t < 4; t++) {
            int q = tid + t * 256, r = q >> 3, ch = q & 7;
            uint32_t so = SW((uint32_t)(r * 128 + ch * 16));
            size_t go = (size_t)r * N_TOK + k0 + ch * 8;
            cpa16(base + so,         Ah + go);
            cpa16(base + 16384 + so, Al + go);
            cpa16(base + 32768 + so, Bh + go);
            cpa16(base + 49152 + so, Bl + go);
        }
        CP_COMMIT();
    };

    load(0);
#pragma unroll 1
    for (int c = 0; c < 32; c++) {
        if (c < 31) { load(c + 1); CP_WAIT(1); } else { CP_WAIT(0); }
        __syncthreads();
        uint32_t base = sb + (c & 1) * 65536;
        mma_chunk(base, base + 16384, base + 32768, base + 49152, aRow, bRow, acc);
        __syncthreads();
    }

    // Epilogue: scale by 1/rowsum, store, global sumsq.
    const int tq = lane >> 2, tr = lane & 3;
    float ssq = 0.f;
#pragma unroll
    for (int mi = 0; mi < 2; mi++)
#pragma unroll
        for (int rh = 0; rh < 2; rh++) {
            int row = row0 + mbase + mi * 16 + rh * 8 + tq;
            float inv = 1.f / g_rowsum[b * N_TOK + row];
#pragma unroll
            for (int ni = 0; ni < 8; ni++) {
                float v0 = acc[mi][ni][rh * 2 + 0] * inv;
                float v1 = acc[mi][ni][rh * 2 + 1] * inv;
                ssq = fmaf(v0, v0, fmaf(v1, v1, ssq));
                *(float2*)(out + ((size_t)row * B_SZ + b) * H_DIM
                               + col0 + nbase + ni * 8 + tr * 2) = make_float2(v0, v1);
            }
        }
#pragma unroll
    for (int o = 16; o; o >>= 1) ssq += __shfl_xor_sync(0xffffffffu, ssq, o);
    float* red = (float*)smem_raw;
    __syncthreads();
    if (lane == 0) red[w] = ssq;
    __syncthreads();
    if (tid == 0) {
        float s = 0.f;
#pragma unroll
        for (int i = 0; i < 8; i++) s += red[i];
        atomicAdd(&g_sumsq[0], s);
    }
}

// ---------------------------------------------------------------------------
// Kernel 4: out *= rsqrt(sum(out^2))
// ---------------------------------------------------------------------------
__global__ void k_scale(float* __restrict__ out) {
    float s = rsqrtf(g_sumsq[0]);
    const int total4 = (N_TOK * B_SZ * H_DIM) / 4;
    float4* o4 = (float4*)out;
    for (int i = blockIdx.x * blockDim.x + threadIdx.x; i < total4;
         i += gridDim.x * blockDim.x) {
        float4 v = o4[i];
        v.x *= s; v.y *= s; v.z *= s; v.w *= s;
        o4[i] = v;
    }
}

extern "C" void kernel_launch(void* const* d_in, const int* in_sizes, int n_in,
                              void* d_out, int out_size) {
    (void)in_sizes; (void)n_in; (void)out_size;
    const float* x = (const float*)d_in[0];
    const float* h = (const float*)d_in[1];
    float* out = (float*)d_out;

    cudaFuncSetAttribute(k_qk, cudaFuncAttributeMaxDynamicSharedMemorySize, GEMM_SMEM);
    cudaFuncSetAttribute(k_pv, cudaFuncAttributeMaxDynamicSharedMemorySize, GEMM_SMEM);

    k_normalize<<<(B_SZ * N_TOK) / 8, 256>>>(x);
    k_ht<<<dim3(N_TOK / 32, H_DIM / 32, B_SZ), dim3(32, 8)>>>(h);
    k_qk<<<dim3(16, 16, B_SZ), 256, GEMM_SMEM>>>();
    k_pv<<<dim3(4, 16, B_SZ), 256, GEMM_SMEM>>>(out);
    k_scale<<<1024, 256>>>(out);
}

// round 6
// speedup vs baseline: 3.2966x; 1.7877x over previous
#include <cuda_runtime.h>
#include <cuda_fp16.h>
#include <cstdint>

#define N_TOK 2048
#define B_SZ  8
#define E_DIM 256
#define H_DIM 512

// ---------------------------------------------------------------------------
// Scratch (static device globals — no runtime allocation).
// ---------------------------------------------------------------------------
__device__ __half g_x[(size_t)B_SZ * N_TOK * E_DIM];    // xn fp16 (B,N,E)
__device__ __half g_hth[(size_t)B_SZ * H_DIM * N_TOK];  // h^T hi (B,H,N)
__device__ __half g_htl[(size_t)B_SZ * H_DIM * N_TOK];  // h^T lo
__device__ __half g_P[(size_t)B_SZ * N_TOK * N_TOK];    // exp(scores) fp16
__device__ float g_rowsum[B_SZ * N_TOK];
__device__ float g_sumsq[1];

// ---------------------------------------------------------------------------
// Helpers (plain sm_103-compatible PTX: ldmatrix / mma.sync / cp.async)
// ---------------------------------------------------------------------------
__device__ __forceinline__ uint32_t smem_u32(const void* p) {
    uint32_t a;
    asm("{ .reg .u64 t; cvta.to.shared.u64 t, %1; cvt.u32.u64 %0, t; }" : "=r"(a) : "l"(p));
    return a;
}
__device__ __forceinline__ void cpa16(uint32_t dst, const void* src) {
    asm volatile("cp.async.cg.shared.global [%0], [%1], 16;"
                 :: "r"(dst), "l"(__cvta_generic_to_global(src)));
}
#define CP_COMMIT() asm volatile("cp.async.commit_group;" ::: "memory")
#define CP_WAIT(n)  asm volatile("cp.async.wait_group %0;" :: "n"(n) : "memory")

#define LDSM4(r0, r1, r2, r3, addr) \
    asm volatile("ldmatrix.sync.aligned.m8n8.x4.shared.b16 {%0,%1,%2,%3}, [%4];" \
                 : "=r"(r0), "=r"(r1), "=r"(r2), "=r"(r3) : "r"(addr))

#define MMA(c, a, b0, b1) \
    asm volatile("mma.sync.aligned.m16n8k16.row.col.f32.f16.f16.f32 " \
                 "{%0,%1,%2,%3},{%4,%5,%6,%7},{%8,%9},{%0,%1,%2,%3};" \
                 : "+f"((c)[0]), "+f"((c)[1]), "+f"((c)[2]), "+f"((c)[3]) \
                 : "r"((a)[0]), "r"((a)[1]), "r"((a)[2]), "r"((a)[3]), "r"(b0), "r"(b1))

// SW128 swizzle: 128-byte rows, xor bits[6:4] ^= bits[9:7]
#define SW(o) ((o) ^ (((o) >> 3) & 0x70u))

__device__ __forceinline__ void split_f16(float v, __half& hi, __half& lo) {
    hi = __float2half_rn(v);
    lo = __float2half_rn(v - __half2float(hi));
}

// per-lane ldmatrix row offsets (128-byte tile rows)
__device__ __forceinline__ uint32_t a_row_off(int mbase, int lane) {
    int row = mbase + (lane & 7) + ((lane >> 3) & 1) * 8;
    return (uint32_t)(row * 128 + (lane >> 4) * 16);
}
__device__ __forceinline__ uint32_t b_row_off(int nbase, int lane) {
    int row = nbase + (lane & 7) + ((lane >> 4) << 3);
    return (uint32_t)(row * 128 + ((lane >> 3) & 1) * 16);
}

#define QK_SMEM (1024 + 2 * 32768)
#define PV_SMEM (1024 + 2 * 49152)

// ---------------------------------------------------------------------------
// Kernel 1: row-normalize x (N,B,E) -> fp16 (B,N,E); zero accumulators.
// ---------------------------------------------------------------------------
__global__ __launch_bounds__(256) void k_normalize(const float* __restrict__ x) {
    if (blockIdx.x == 0) {
        for (int i = threadIdx.x; i < B_SZ * N_TOK; i += blockDim.x) g_rowsum[i] = 0.f;
        if (threadIdx.x == 0) g_sumsq[0] = 0.f;
    }
    int warp = (blockIdx.x * blockDim.x + threadIdx.x) >> 5;
    int lane = threadIdx.x & 31;
    if (warp >= B_SZ * N_TOK) return;
    int b = warp / N_TOK, i = warp % N_TOK;

    const float4* row = (const float4*)(x + ((size_t)i * B_SZ + b) * E_DIM);
    float4 v0 = row[lane], v1 = row[lane + 32];
    float ss = v0.x*v0.x + v0.y*v0.y + v0.z*v0.z + v0.w*v0.w
             + v1.x*v1.x + v1.y*v1.y + v1.z*v1.z + v1.w*v1.w;
#pragma unroll
    for (int o = 16; o; o >>= 1) ss += __shfl_xor_sync(0xffffffffu, ss, o);
    float r = rsqrtf(ss);

    size_t base = ((size_t)b * N_TOK + i) * E_DIM;
    float v[8] = {v0.x*r, v0.y*r, v0.z*r, v0.w*r, v1.x*r, v1.y*r, v1.z*r, v1.w*r};
#pragma unroll
    for (int half = 0; half < 2; half++) {
        int col = half * 128 + lane * 4;
        union { __half h4[4]; uint2 u; } uu;
#pragma unroll
        for (int k = 0; k < 4; k++) uu.h4[k] = __float2half_rn(v[half*4+k]);
        *(uint2*)(g_x + base + col) = uu.u;
    }
}

// ---------------------------------------------------------------------------
// Kernel 1b: transpose h (N,B,H) -> (B,H,N), split to fp16 hi/lo.
// ---------------------------------------------------------------------------
__global__ void k_ht(const float* __restrict__ h) {
    __shared__ float t[32][33];
    int b = blockIdx.z, tok0 = blockIdx.x * 32, hc0 = blockIdx.y * 32;
    int tx = threadIdx.x, ty = threadIdx.y;
#pragma unroll
    for (int k = 0; k < 4; k++)
        t[ty + 8*k][tx] = h[(size_t)(tok0 + ty + 8*k) * (B_SZ*H_DIM) + b*H_DIM + hc0 + tx];
    __syncthreads();
#pragma unroll
    for (int k = 0; k < 4; k++) {
        int r = ty + 8*k;
        float v = t[tx][r];
        __half hi, lo; split_f16(v, hi, lo);
        size_t o = ((size_t)b * H_DIM + hc0 + r) * N_TOK + tok0 + tx;
        g_hth[o] = hi; g_htl[o] = lo;
    }
}

// ---------------------------------------------------------------------------
// Kernel 2: QK. CTA 128x128, single-pass fp16: P = exp(xn . xn^T) -> fp16,
// fused rowsum atomics. 2-stage cp.async pipeline, SW128 tiles.
// ---------------------------------------------------------------------------
__global__ __launch_bounds__(256, 2) void k_qk() {
    extern __shared__ char smem_raw[];
    uint32_t sb = (smem_u32(smem_raw) + 1023) & ~1023u;
    const int tid = threadIdx.x, lane = tid & 31, w = tid >> 5;
    const int b = blockIdx.z, row0 = blockIdx.y * 128, col0 = blockIdx.x * 128;

    const __half* A = g_x + ((size_t)b * N_TOK + row0) * E_DIM;
    const __half* B = g_x + ((size_t)b * N_TOK + col0) * E_DIM;

    const int mbase = (w & 3) * 32, nbase = (w >> 2) * 64;
    const uint32_t aRow = a_row_off(mbase, lane);
    const uint32_t bRow = b_row_off(nbase, lane);
    float acc[2][8][4] = {};

    auto load = [&](int c) {
        uint32_t base = sb + (c & 1) * 32768;
        int k0 = c * 64;
#pragma unroll
        for (int t = 0; t < 4; t++) {
            int q = tid + t * 256, r = q >> 3, ch = q & 7;
            uint32_t so = SW((uint32_t)(r * 128 + ch * 16));
            size_t go = (size_t)r * E_DIM + k0 + ch * 8;
            cpa16(base + so,         A + go);
            cpa16(base + 16384 + so, B + go);
        }
        CP_COMMIT();
    };

    load(0);
#pragma unroll 1
    for (int c = 0; c < 4; c++) {
        if (c < 3) { load(c + 1); CP_WAIT(1); } else { CP_WAIT(0); }
        __syncthreads();
        uint32_t aB = sb + (c & 1) * 32768, bB = aB + 16384;
#pragma unroll
        for (int k16 = 0; k16 < 4; k16++) {
            uint32_t aoff = SW(aRow + k16 * 32);
            uint32_t boff = SW(bRow + k16 * 32);
            uint32_t af[2][4], bf[4][4];
#pragma unroll
            for (int mi = 0; mi < 2; mi++)
                LDSM4(af[mi][0], af[mi][1], af[mi][2], af[mi][3], aB + aoff + mi * 2048);
#pragma unroll
            for (int g = 0; g < 4; g++)
                LDSM4(bf[g][0], bf[g][1], bf[g][2], bf[g][3], bB + boff + g * 2048);
#pragma unroll
            for (int mi = 0; mi < 2; mi++)
#pragma unroll
                for (int ni = 0; ni < 8; ni++) {
                    const int g = ni >> 1, p = (ni & 1) * 2;
                    MMA(acc[mi][ni], af[mi], bf[g][p], bf[g][p + 1]);
                }
        }
        __syncthreads();
    }

    // Epilogue: exp, rowsum atomics, fp16 store of P.
    const int tq = lane >> 2, tr = lane & 3;
    __half* Pb = g_P + (size_t)b * N_TOK * N_TOK;
#pragma unroll
    for (int mi = 0; mi < 2; mi++)
#pragma unroll
        for (int rh = 0; rh < 2; rh++) {
            int row = row0 + mbase + mi * 16 + rh * 8 + tq;
            float rs = 0.f;
#pragma unroll
            for (int ni = 0; ni < 8; ni++) {
                float e0 = __expf(acc[mi][ni][rh * 2 + 0]);
                float e1 = __expf(acc[mi][ni][rh * 2 + 1]);
                rs += e0 + e1;
                __half2 hv = __floats2half2_rn(e0, e1);
                *(uint32_t*)(Pb + (size_t)row * N_TOK + col0 + nbase + ni * 8 + tr * 2)
                    = *(uint32_t*)&hv;
            }
            rs += __shfl_xor_sync(0xffffffffu, rs, 1);
            rs += __shfl_xor_sync(0xffffffffu, rs, 2);
            if (tr == 0) atomicAdd(&g_rowsum[b * N_TOK + row], rs);
        }
}

// ---------------------------------------------------------------------------
// Kernel 3: PV. CTA 128x128, out = (P . h^T)/rowsum, 2 passes (P fp16 single,
// h^T fp16 hi/lo split). 2-stage cp.async pipeline. Global sumsq.
// ---------------------------------------------------------------------------
__global__ __launch_bounds__(256, 2) void k_pv(float* __restrict__ out) {
    extern __shared__ char smem_raw[];
    uint32_t sb = (smem_u32(smem_raw) + 1023) & ~1023u;
    const int tid = threadIdx.x, lane = tid & 31, w = tid >> 5;
    const int b = blockIdx.z, row0 = blockIdx.y * 128, col0 = blockIdx.x * 128;

    const __half* A  = g_P  + ((size_t)b * N_TOK + row0) * N_TOK;
    const __half* Bh = g_hth + ((size_t)b * H_DIM + col0) * N_TOK;
    const __half* Bl = g_htl + ((size_t)b * H_DIM + col0) * N_TOK;

    const int mbase = (w & 3) * 32, nbase = (w >> 2) * 64;
    const uint32_t aRow = a_row_off(mbase, lane);
    const uint32_t bRow = b_row_off(nbase, lane);
    float acc[2][8][4] = {};

    auto load = [&](int c) {
        uint32_t base = sb + (c & 1) * 49152;
        int k0 = c * 64;
#pragma unroll
        for (int t = 0; t < 4; t++) {
            int q = tid + t * 256, r = q >> 3, ch = q & 7;
            uint32_t so = SW((uint32_t)(r * 128 + ch * 16));
            size_t go = (size_t)r * N_TOK + k0 + ch * 8;
            cpa16(base + so,         A + go);
            cpa16(base + 16384 + so, Bh + go);
            cpa16(base + 32768 + so, Bl + go);
        }
        CP_COMMIT();
    };

    load(0);
#pragma unroll 1
    for (int c = 0; c < 32; c++) {
        if (c < 31) { load(c + 1); CP_WAIT(1); } else { CP_WAIT(0); }
        __syncthreads();
        uint32_t aB = sb + (c & 1) * 49152, bhB = aB + 16384, blB = aB + 32768;
#pragma unroll
        for (int k16 = 0; k16 < 4; k16++) {
            uint32_t aoff = SW(aRow + k16 * 32);
            uint32_t boff = SW(bRow + k16 * 32);
            uint32_t af[2][4], bh[4][4], bl[4][4];
#pragma unroll
            for (int mi = 0; mi < 2; mi++)
                LDSM4(af[mi][0], af[mi][1], af[mi][2], af[mi][3], aB + aoff + mi * 2048);
#pragma unroll
            for (int g = 0; g < 4; g++) {
                LDSM4(bh[g][0], bh[g][1], bh[g][2], bh[g][3], bhB + boff + g * 2048);
                LDSM4(bl[g][0], bl[g][1], bl[g][2], bl[g][3], blB + boff + g * 2048);
            }
#pragma unroll
            for (int mi = 0; mi < 2; mi++)
#pragma unroll
                for (int ni = 0; ni < 8; ni++) {
                    const int g = ni >> 1, p = (ni & 1) * 2;
                    MMA(acc[mi][ni], af[mi], bh[g][p], bh[g][p + 1]);
                    MMA(acc[mi][ni], af[mi], bl[g][p], bl[g][p + 1]);
                }
        }
        __syncthreads();
    }

    // Epilogue: scale by 1/rowsum, store, global sumsq.
    const int tq = lane >> 2, tr = lane & 3;
    float ssq = 0.f;
#pragma unroll
    for (int mi = 0; mi < 2; mi++)
#pragma unroll
        for (int rh = 0; rh < 2; rh++) {
            int row = row0 + mbase + mi * 16 + rh * 8 + tq;
            float inv = 1.f / g_rowsum[b * N_TOK + row];
#pragma unroll
            for (int ni = 0; ni < 8; ni++) {
                float v0 = acc[mi][ni][rh * 2 + 0] * inv;
                float v1 = acc[mi][ni][rh * 2 + 1] * inv;
                ssq = fmaf(v0, v0, fmaf(v1, v1, ssq));
                *(float2*)(out + ((size_t)row * B_SZ + b) * H_DIM
                               + col0 + nbase + ni * 8 + tr * 2) = make_float2(v0, v1);
            }
        }
#pragma unroll
    for (int o = 16; o; o >>= 1) ssq += __shfl_xor_sync(0xffffffffu, ssq, o);
    float* red = (float*)smem_raw;
    __syncthreads();
    if (lane == 0) red[w] = ssq;
    __syncthreads();
    if (tid == 0) {
        float s = 0.f;
#pragma unroll
        for (int i = 0; i < 8; i++) s += red[i];
        atomicAdd(&g_sumsq[0], s);
    }
}

// ---------------------------------------------------------------------------
// Kernel 4: out *= rsqrt(sum(out^2))
// ---------------------------------------------------------------------------
__global__ void k_scale(float* __restrict__ out) {
    float s = rsqrtf(g_sumsq[0]);
    const int total4 = (N_TOK * B_SZ * H_DIM) / 4;
    float4* o4 = (float4*)out;
    for (int i = blockIdx.x * blockDim.x + threadIdx.x; i < total4;
         i += gridDim.x * blockDim.x) {
        float4 v = o4[i];
        v.x *= s; v.y *= s; v.z *= s; v.w *= s;
        o4[i] = v;
    }
}

extern "C" void kernel_launch(void* const* d_in, const int* in_sizes, int n_in,
                              void* d_out, int out_size) {
    (void)in_sizes; (void)n_in; (void)out_size;
    const float* x = (const float*)d_in[0];
    const float* h = (const float*)d_in[1];
    float* out = (float*)d_out;

    cudaFuncSetAttribute(k_qk, cudaFuncAttributeMaxDynamicSharedMemorySize, QK_SMEM);
    cudaFuncSetAttribute(k_pv, cudaFuncAttributeMaxDynamicSharedMemorySize, PV_SMEM);

    k_normalize<<<(B_SZ * N_TOK) / 8, 256>>>(x);
    k_ht<<<dim3(N_TOK / 32, H_DIM / 32, B_SZ), dim3(32, 8)>>>(h);
    k_qk<<<dim3(16, 16, B_SZ), 256, QK_SMEM>>>();
    k_pv<<<dim3(4, 16, B_SZ), 256, PV_SMEM>>>(out);
    k_scale<<<1024, 256>>>(out);
}

// round 8
// speedup vs baseline: 7.1678x; 2.1743x over previous
#include <cuda_runtime.h>
#include <cuda_fp16.h>
#include <cstdint>

#define N_TOK 2048
#define B_SZ  8
#define E_DIM 256
#define H_DIM 512

// ---------------------------------------------------------------------------
// Scratch (static device globals — no runtime allocation).
// ---------------------------------------------------------------------------
__device__ __half g_x[(size_t)B_SZ * N_TOK * E_DIM];    // xn fp16 (B,N,E)
__device__ __half g_hth[(size_t)B_SZ * H_DIM * N_TOK];  // h^T fp16 (B,H,N)
__device__ __half g_P[(size_t)B_SZ * N_TOK * N_TOK];    // exp(scores) fp16
__device__ float g_rowsum[B_SZ * N_TOK];
__device__ float g_sumsq[1];

// ---------------------------------------------------------------------------
// Helpers (plain sm_103-compatible PTX: ldmatrix / mma.sync / cp.async)
// ---------------------------------------------------------------------------
__device__ __forceinline__ uint32_t smem_u32(const void* p) {
    uint32_t a;
    asm("{ .reg .u64 t; cvta.to.shared.u64 t, %1; cvt.u32.u64 %0, t; }" : "=r"(a) : "l"(p));
    return a;
}
__device__ __forceinline__ void cpa16(uint32_t dst, const void* src) {
    asm volatile("cp.async.cg.shared.global [%0], [%1], 16;"
                 :: "r"(dst), "l"(__cvta_generic_to_global(src)));
}
#define CP_COMMIT() asm volatile("cp.async.commit_group;" ::: "memory")
#define CP_WAIT(n)  asm volatile("cp.async.wait_group %0;" :: "n"(n) : "memory")

#define LDSM4(r0, r1, r2, r3, addr) \
    asm volatile("ldmatrix.sync.aligned.m8n8.x4.shared.b16 {%0,%1,%2,%3}, [%4];" \
                 : "=r"(r0), "=r"(r1), "=r"(r2), "=r"(r3) : "r"(addr))

#define MMA(c, a, b0, b1) \
    asm volatile("mma.sync.aligned.m16n8k16.row.col.f32.f16.f16.f32 " \
                 "{%0,%1,%2,%3},{%4,%5,%6,%7},{%8,%9},{%0,%1,%2,%3};" \
                 : "+f"((c)[0]), "+f"((c)[1]), "+f"((c)[2]), "+f"((c)[3]) \
                 : "r"((a)[0]), "r"((a)[1]), "r"((a)[2]), "r"((a)[3]), "r"(b0), "r"(b1))

// SW128 swizzle: 128-byte rows, xor bits[6:4] ^= bits[9:7]
#define SW(o) ((o) ^ (((o) >> 3) & 0x70u))

// per-lane ldmatrix row offsets (128-byte tile rows)
__device__ __forceinline__ uint32_t a_row_off(int mbase, int lane) {
    int row = mbase + (lane & 7) + ((lane >> 3) & 1) * 8;
    return (uint32_t)(row * 128 + (lane >> 4) * 16);
}
__device__ __forceinline__ uint32_t b_row_off(int nbase, int lane) {
    int row = nbase + (lane & 7) + ((lane >> 4) << 3);
    return (uint32_t)(row * 128 + ((lane >> 3) & 1) * 16);
}

#define QK_SMEM (1024 + 2 * 32768)
#define PV_SMEM (1024 + 2 * 32768)

// ---------------------------------------------------------------------------
// Kernel 1: row-normalize x (N,B,E) -> fp16 (B,N,E); zero accumulators.
// ---------------------------------------------------------------------------
__global__ __launch_bounds__(256) void k_normalize(const float* __restrict__ x) {
    if (blockIdx.x == 0) {
        for (int i = threadIdx.x; i < B_SZ * N_TOK; i += blockDim.x) g_rowsum[i] = 0.f;
        if (threadIdx.x == 0) g_sumsq[0] = 0.f;
    }
    int warp = (blockIdx.x * blockDim.x + threadIdx.x) >> 5;
    int lane = threadIdx.x & 31;
    if (warp >= B_SZ * N_TOK) return;
    int b = warp / N_TOK, i = warp % N_TOK;

    const float4* row = (const float4*)(x + ((size_t)i * B_SZ + b) * E_DIM);
    float4 v0 = row[lane], v1 = row[lane + 32];
    float ss = v0.x*v0.x + v0.y*v0.y + v0.z*v0.z + v0.w*v0.w
             + v1.x*v1.x + v1.y*v1.y + v1.z*v1.z + v1.w*v1.w;
#pragma unroll
    for (int o = 16; o; o >>= 1) ss += __shfl_xor_sync(0xffffffffu, ss, o);
    float r = rsqrtf(ss);

    size_t base = ((size_t)b * N_TOK + i) * E_DIM;
    float v[8] = {v0.x*r, v0.y*r, v0.z*r, v0.w*r, v1.x*r, v1.y*r, v1.z*r, v1.w*r};
#pragma unroll
    for (int half = 0; half < 2; half++) {
        int col = half * 128 + lane * 4;
        union { __half h4[4]; uint2 u; } uu;
#pragma unroll
        for (int k = 0; k < 4; k++) uu.h4[k] = __float2half_rn(v[half*4+k]);
        *(uint2*)(g_x + base + col) = uu.u;
    }
}

// ---------------------------------------------------------------------------
// Kernel 1b: transpose h (N,B,H) -> (B,H,N) fp16.
// ---------------------------------------------------------------------------
__global__ void k_ht(const float* __restrict__ h) {
    __shared__ float t[32][33];
    int b = blockIdx.z, tok0 = blockIdx.x * 32, hc0 = blockIdx.y * 32;
    int tx = threadIdx.x, ty = threadIdx.y;
#pragma unroll
    for (int k = 0; k < 4; k++)
        t[ty + 8*k][tx] = h[(size_t)(tok0 + ty + 8*k) * (B_SZ*H_DIM) + b*H_DIM + hc0 + tx];
    __syncthreads();
#pragma unroll
    for (int k = 0; k < 4; k++) {
        int r = ty + 8*k;
        g_hth[((size_t)b * H_DIM + hc0 + r) * N_TOK + tok0 + tx] = __float2half_rn(t[tx][r]);
    }
}

// ---------------------------------------------------------------------------
// Kernel 2: QK. CTA 128x128, single-pass fp16: P = exp(xn . xn^T) -> fp16,
// fused rowsum atomics. 2-stage cp.async pipeline, SW128 tiles.
// ---------------------------------------------------------------------------
__global__ __launch_bounds__(256, 2) void k_qk() {
    extern __shared__ char smem_raw[];
    uint32_t sb = (smem_u32(smem_raw) + 1023) & ~1023u;
    const int tid = threadIdx.x, lane = tid & 31, w = tid >> 5;
    const int b = blockIdx.z, row0 = blockIdx.y * 128, col0 = blockIdx.x * 128;

    const __half* A = g_x + ((size_t)b * N_TOK + row0) * E_DIM;
    const __half* B = g_x + ((size_t)b * N_TOK + col0) * E_DIM;

    const int mbase = (w & 3) * 32, nbase = (w >> 2) * 64;
    const uint32_t aRow = a_row_off(mbase, lane);
    const uint32_t bRow = b_row_off(nbase, lane);
    float acc[2][8][4] = {};

    auto load = [&](int c) {
        uint32_t base = sb + (c & 1) * 32768;
        int k0 = c * 64;
#pragma unroll
        for (int t = 0; t < 4; t++) {
            int q = tid + t * 256, r = q >> 3, ch = q & 7;
            uint32_t so = SW((uint32_t)(r * 128 + ch * 16));
            size_t go = (size_t)r * E_DIM + k0 + ch * 8;
            cpa16(base + so,         A + go);
            cpa16(base + 16384 + so, B + go);
        }
        CP_COMMIT();
    };

    load(0);
#pragma unroll 1
    for (int c = 0; c < 4; c++) {
        if (c < 3) { load(c + 1); CP_WAIT(1); } else { CP_WAIT(0); }
        __syncthreads();
        uint32_t aB = sb + (c & 1) * 32768, bB = aB + 16384;
#pragma unroll
        for (int k16 = 0; k16 < 4; k16++) {
            uint32_t aoff = SW(aRow + k16 * 32);
            uint32_t boff = SW(bRow + k16 * 32);
            uint32_t af[2][4], bf[4][4];
#pragma unroll
            for (int mi = 0; mi < 2; mi++)
                LDSM4(af[mi][0], af[mi][1], af[mi][2], af[mi][3], aB + aoff + mi * 2048);
#pragma unroll
            for (int g = 0; g < 4; g++)
                LDSM4(bf[g][0], bf[g][1], bf[g][2], bf[g][3], bB + boff + g * 2048);
#pragma unroll
            for (int mi = 0; mi < 2; mi++)
#pragma unroll
                for (int ni = 0; ni < 8; ni++) {
                    const int g = ni >> 1, p = (ni & 1) * 2;
                    MMA(acc[mi][ni], af[mi], bf[g][p], bf[g][p + 1]);
                }
        }
        __syncthreads();
    }

    // Epilogue: exp, rowsum atomics, fp16 store of P.
    const int tq = lane >> 2, tr = lane & 3;
    __half* Pb = g_P + (size_t)b * N_TOK * N_TOK;
#pragma unroll
    for (int mi = 0; mi < 2; mi++)
#pragma unroll
        for (int rh = 0; rh < 2; rh++) {
            int row = row0 + mbase + mi * 16 + rh * 8 + tq;
            float rs = 0.f;
#pragma unroll
            for (int ni = 0; ni < 8; ni++) {
                float e0 = __expf(acc[mi][ni][rh * 2 + 0]);
                float e1 = __expf(acc[mi][ni][rh * 2 + 1]);
                rs += e0 + e1;
                __half2 hv = __floats2half2_rn(e0, e1);
                *(uint32_t*)(Pb + (size_t)row * N_TOK + col0 + nbase + ni * 8 + tr * 2)
                    = *(uint32_t*)&hv;
            }
            rs += __shfl_xor_sync(0xffffffffu, rs, 1);
            rs += __shfl_xor_sync(0xffffffffu, rs, 2);
            if (tr == 0) atomicAdd(&g_rowsum[b * N_TOK + row], rs);
        }
}

// ---------------------------------------------------------------------------
// Kernel 3: PV. CTA 128x128, out = (P . h^T)/rowsum, single fp16 pass.
// 2-stage cp.async pipeline. Global sumsq.
// ---------------------------------------------------------------------------
__global__ __launch_bounds__(256, 2) void k_pv(float* __restrict__ out) {
    extern __shared__ char smem_raw[];
    uint32_t sb = (smem_u32(smem_raw) + 1023) & ~1023u;
    const int tid = threadIdx.x, lane = tid & 31, w = tid >> 5;
    const int b = blockIdx.z, row0 = blockIdx.y * 128, col0 = blockIdx.x * 128;

    const __half* A  = g_P   + ((size_t)b * N_TOK + row0) * N_TOK;
    const __half* Bh = g_hth + ((size_t)b * H_DIM + col0) * N_TOK;

    const int mbase = (w & 3) * 32, nbase = (w >> 2) * 64;
    const uint32_t aRow = a_row_off(mbase, lane);
    const uint32_t bRow = b_row_off(nbase, lane);
    float acc[2][8][4] = {};

    auto load = [&](int c) {
        uint32_t base = sb + (c & 1) * 32768;
        int k0 = c * 64;
#pragma unroll
        for (int t = 0; t < 4; t++) {
            int q = tid + t * 256, r = q >> 3, ch = q & 7;
            uint32_t so = SW((uint32_t)(r * 128 + ch * 16));
            size_t go = (size_t)r * N_TOK + k0 + ch * 8;
            cpa16(base + so,         A + go);
            cpa16(base + 16384 + so, Bh + go);
        }
        CP_COMMIT();
    };

    load(0);
#pragma unroll 1
    for (int c = 0; c < 32; c++) {
        if (c < 31) { load(c + 1); CP_WAIT(1); } else { CP_WAIT(0); }
        __syncthreads();
        uint32_t aB = sb + (c & 1) * 32768, bB = aB + 16384;
#pragma unroll
        for (int k16 = 0; k16 < 4; k16++) {
            uint32_t aoff = SW(aRow + k16 * 32);
            uint32_t boff = SW(bRow + k16 * 32);
            uint32_t af[2][4], bf[4][4];
#pragma unroll
            for (int mi = 0; mi < 2; mi++)
                LDSM4(af[mi][0], af[mi][1], af[mi][2], af[mi][3], aB + aoff + mi * 2048);
#pragma unroll
            for (int g = 0; g < 4; g++)
                LDSM4(bf[g][0], bf[g][1], bf[g][2], bf[g][3], bB + boff + g * 2048);
#pragma unroll
            for (int mi = 0; mi < 2; mi++)
#pragma unroll
                for (int ni = 0; ni < 8; ni++) {
                    const int g = ni >> 1, p = (ni & 1) * 2;
                    MMA(acc[mi][ni], af[mi], bf[g][p], bf[g][p + 1]);
                }
        }
        __syncthreads();
    }

    // Epilogue: scale by 1/rowsum, store, global sumsq.
    const int tq = lane >> 2, tr = lane & 3;
    float ssq = 0.f;
#pragma unroll
    for (int mi = 0; mi < 2; mi++)
#pragma unroll
        for (int rh = 0; rh < 2; rh++) {
            int row = row0 + mbase + mi * 16 + rh * 8 + tq;
            float inv = 1.f / g_rowsum[b * N_TOK + row];
#pragma unroll
            for (int ni = 0; ni < 8; ni++) {
                float v0 = acc[mi][ni][rh * 2 + 0] * inv;
                float v1 = acc[mi][ni][rh * 2 + 1] * inv;
                ssq = fmaf(v0, v0, fmaf(v1, v1, ssq));
                *(float2*)(out + ((size_t)row * B_SZ + b) * H_DIM
                               + col0 + nbase + ni * 8 + tr * 2) = make_float2(v0, v1);
            }
        }
#pragma unroll
    for (int o = 16; o; o >>= 1) ssq += __shfl_xor_sync(0xffffffffu, ssq, o);
    float* red = (float*)smem_raw;
    __syncthreads();
    if (lane == 0) red[w] = ssq;
    __syncthreads();
    if (tid == 0) {
        float s = 0.f;
#pragma unroll
        for (int i = 0; i < 8; i++) s += red[i];
        atomicAdd(&g_sumsq[0], s);
    }
}

// ---------------------------------------------------------------------------
// Kernel 4: out *= rsqrt(sum(out^2))
// ---------------------------------------------------------------------------
__global__ void k_scale(float* __restrict__ out) {
    float s = rsqrtf(g_sumsq[0]);
    const int total4 = (N_TOK * B_SZ * H_DIM) / 4;
    float4* o4 = (float4*)out;
    for (int i = blockIdx.x * blockDim.x + threadIdx.x; i < total4;
         i += gridDim.x * blockDim.x) {
        float4 v = o4[i];
        v.x *= s; v.y *= s; v.z *= s; v.w *= s;
        o4[i] = v;
    }
}

extern "C" void kernel_launch(void* const* d_in, const int* in_sizes, int n_in,
                              void* d_out, int out_size) {
    (void)in_sizes; (void)n_in; (void)out_size;
    const float* x = (const float*)d_in[0];
    const float* h = (const float*)d_in[1];
    float* out = (float*)d_out;

    cudaFuncSetAttribute(k_qk, cudaFuncAttributeMaxDynamicSharedMemorySize, QK_SMEM);
    cudaFuncSetAttribute(k_pv, cudaFuncAttributeMaxDynamicSharedMemorySize, PV_SMEM);

    k_normalize<<<(B_SZ * N_TOK) / 8, 256>>>(x);
    k_ht<<<dim3(N_TOK / 32, H_DIM / 32, B_SZ), dim3(32, 8)>>>(h);
    k_qk<<<dim3(16, 16, B_SZ), 256, QK_SMEM>>>();
    k_pv<<<dim3(4, 16, B_SZ), 256, PV_SMEM>>>(out);
    k_scale<<<1024, 256>>>(out);
}

// round 9
// speedup vs baseline: 7.7497x; 1.0812x over previous
#include <cuda_runtime.h>
#include <cuda_fp16.h>
#include <cstdint>

#define N_TOK 2048
#define B_SZ  8
#define E_DIM 256
#define H_DIM 512

// ---------------------------------------------------------------------------
// Scratch (static device globals — no runtime allocation).
// ---------------------------------------------------------------------------
__device__ __half g_x[(size_t)B_SZ * N_TOK * E_DIM];    // xn fp16 (B,N,E)
__device__ __half g_hth[(size_t)B_SZ * H_DIM * N_TOK];  // h^T fp16 (B,H,N)
__device__ __half g_P[(size_t)B_SZ * N_TOK * N_TOK];    // exp(scores) fp16
__device__ float g_rowsum[B_SZ * N_TOK];
__device__ float g_sumsq[1];

// ---------------------------------------------------------------------------
// Helpers (plain sm_103-compatible PTX: ldmatrix / mma.sync / cp.async)
// ---------------------------------------------------------------------------
__device__ __forceinline__ uint32_t smem_u32(const void* p) {
    uint32_t a;
    asm("{ .reg .u64 t; cvta.to.shared.u64 t, %1; cvt.u32.u64 %0, t; }" : "=r"(a) : "l"(p));
    return a;
}
__device__ __forceinline__ void cpa16(uint32_t dst, const void* src) {
    asm volatile("cp.async.cg.shared.global [%0], [%1], 16;"
                 :: "r"(dst), "l"(__cvta_generic_to_global(src)));
}
#define CP_COMMIT() asm volatile("cp.async.commit_group;" ::: "memory")
#define CP_WAIT(n)  asm volatile("cp.async.wait_group %0;" :: "n"(n) : "memory")

#define LDSM4(r0, r1, r2, r3, addr) \
    asm volatile("ldmatrix.sync.aligned.m8n8.x4.shared.b16 {%0,%1,%2,%3}, [%4];" \
                 : "=r"(r0), "=r"(r1), "=r"(r2), "=r"(r3) : "r"(addr))

#define MMA(c, a, b0, b1) \
    asm volatile("mma.sync.aligned.m16n8k16.row.col.f32.f16.f16.f32 " \
                 "{%0,%1,%2,%3},{%4,%5,%6,%7},{%8,%9},{%0,%1,%2,%3};" \
                 : "+f"((c)[0]), "+f"((c)[1]), "+f"((c)[2]), "+f"((c)[3]) \
                 : "r"((a)[0]), "r"((a)[1]), "r"((a)[2]), "r"((a)[3]), "r"(b0), "r"(b1))

// SW128 swizzle: 128-byte rows, xor bits[6:4] ^= bits[9:7]
#define SW(o) ((o) ^ (((o) >> 3) & 0x70u))

// per-lane ldmatrix row offsets (128-byte tile rows)
__device__ __forceinline__ uint32_t a_row_off(int mbase, int lane) {
    int row = mbase + (lane & 7) + ((lane >> 3) & 1) * 8;
    return (uint32_t)(row * 128 + (lane >> 4) * 16);
}
__device__ __forceinline__ uint32_t b_row_off(int nbase, int lane) {
    int row = nbase + (lane & 7) + ((lane >> 4) << 3);
    return (uint32_t)(row * 128 + ((lane >> 3) & 1) * 16);
}

#define STAGE_BYTES 32768
#define GEMM_SMEM (1024 + 3 * STAGE_BYTES)

// ---------------------------------------------------------------------------
// Kernel 1: row-normalize x (N,B,E) -> fp16 (B,N,E); zero accumulators.
// ---------------------------------------------------------------------------
__global__ __launch_bounds__(256) void k_normalize(const float* __restrict__ x) {
    if (blockIdx.x == 0) {
        for (int i = threadIdx.x; i < B_SZ * N_TOK; i += blockDim.x) g_rowsum[i] = 0.f;
        if (threadIdx.x == 0) g_sumsq[0] = 0.f;
    }
    int warp = (blockIdx.x * blockDim.x + threadIdx.x) >> 5;
    int lane = threadIdx.x & 31;
    if (warp >= B_SZ * N_TOK) return;
    int b = warp / N_TOK, i = warp % N_TOK;

    const float4* row = (const float4*)(x + ((size_t)i * B_SZ + b) * E_DIM);
    float4 v0 = row[lane], v1 = row[lane + 32];
    float ss = v0.x*v0.x + v0.y*v0.y + v0.z*v0.z + v0.w*v0.w
             + v1.x*v1.x + v1.y*v1.y + v1.z*v1.z + v1.w*v1.w;
#pragma unroll
    for (int o = 16; o; o >>= 1) ss += __shfl_xor_sync(0xffffffffu, ss, o);
    float r = rsqrtf(ss);

    size_t base = ((size_t)b * N_TOK + i) * E_DIM;
    float v[8] = {v0.x*r, v0.y*r, v0.z*r, v0.w*r, v1.x*r, v1.y*r, v1.z*r, v1.w*r};
#pragma unroll
    for (int half = 0; half < 2; half++) {
        int col = half * 128 + lane * 4;
        union { __half h4[4]; uint2 u; } uu;
#pragma unroll
        for (int k = 0; k < 4; k++) uu.h4[k] = __float2half_rn(v[half*4+k]);
        *(uint2*)(g_x + base + col) = uu.u;
    }
}

// ---------------------------------------------------------------------------
// Kernel 1b: transpose h (N,B,H) -> (B,H,N) fp16.
// ---------------------------------------------------------------------------
__global__ void k_ht(const float* __restrict__ h) {
    __shared__ float t[32][33];
    int b = blockIdx.z, tok0 = blockIdx.x * 32, hc0 = blockIdx.y * 32;
    int tx = threadIdx.x, ty = threadIdx.y;
#pragma unroll
    for (int k = 0; k < 4; k++)
        t[ty + 8*k][tx] = h[(size_t)(tok0 + ty + 8*k) * (B_SZ*H_DIM) + b*H_DIM + hc0 + tx];
    __syncthreads();
#pragma unroll
    for (int k = 0; k < 4; k++) {
        int r = ty + 8*k;
        g_hth[((size_t)b * H_DIM + hc0 + r) * N_TOK + tok0 + tx] = __float2half_rn(t[tx][r]);
    }
}

// ---------------------------------------------------------------------------
// Kernel 2: QK, symmetric. Grid (136,1,8): lower-triangle 128x128 blocks only.
// P = exp(xn . xn^T); off-diagonal CTAs also emit the transposed block
// (staged via SMEM) and column-sum contributions to rowsum.
// ---------------------------------------------------------------------------
__global__ __launch_bounds__(256, 2) void k_qk() {
    extern __shared__ char smem_raw[];
    uint32_t sb0 = smem_u32(smem_raw);
    uint32_t sb = (sb0 + 1023) & ~1023u;
    char* sbase = smem_raw + (sb - sb0);
    const int tid = threadIdx.x, lane = tid & 31, w = tid >> 5;
    const int b = blockIdx.z;

    // decode lower-triangle block (i, j), j <= i, from linear index
    int bx = blockIdx.x;
    int i = (int)((sqrtf(8.0f * bx + 1.0f) - 1.0f) * 0.5f);
    while ((i + 1) * (i + 2) / 2 <= bx) i++;
    while (i * (i + 1) / 2 > bx) i--;
    int j = bx - i * (i + 1) / 2;
    const int row0 = i * 128, col0 = j * 128;

    const __half* A = g_x + ((size_t)b * N_TOK + row0) * E_DIM;
    const __half* B = g_x + ((size_t)b * N_TOK + col0) * E_DIM;

    const int mbase = (w & 3) * 32, nbase = (w >> 2) * 64;
    const uint32_t aRow = a_row_off(mbase, lane);
    const uint32_t bRow = b_row_off(nbase, lane);
    float acc[2][8][4] = {};

    auto load = [&](int c) {
        uint32_t base = sb + (c % 3) * STAGE_BYTES;
        int k0 = c * 64;
#pragma unroll
        for (int t = 0; t < 4; t++) {
            int q = tid + t * 256, r = q >> 3, ch = q & 7;
            uint32_t so = SW((uint32_t)(r * 128 + ch * 16));
            size_t go = (size_t)r * E_DIM + k0 + ch * 8;
            cpa16(base + so,         A + go);
            cpa16(base + 16384 + so, B + go);
        }
        CP_COMMIT();
    };

    load(0); load(1);
#pragma unroll 1
    for (int c = 0; c < 4; c++) {
        if (c + 2 < 4)      { load(c + 2); CP_WAIT(2); }
        else if (c + 1 < 4) { CP_WAIT(1); }
        else                { CP_WAIT(0); }
        __syncthreads();
        uint32_t aB = sb + (c % 3) * STAGE_BYTES, bB = aB + 16384;
#pragma unroll
        for (int k16 = 0; k16 < 4; k16++) {
            uint32_t aoff = SW(aRow + k16 * 32);
            uint32_t boff = SW(bRow + k16 * 32);
            uint32_t af[2][4], bf[4][4];
#pragma unroll
            for (int mi = 0; mi < 2; mi++)
                LDSM4(af[mi][0], af[mi][1], af[mi][2], af[mi][3], aB + aoff + mi * 2048);
#pragma unroll
            for (int g = 0; g < 4; g++)
                LDSM4(bf[g][0], bf[g][1], bf[g][2], bf[g][3], bB + boff + g * 2048);
#pragma unroll
            for (int mi = 0; mi < 2; mi++)
#pragma unroll
                for (int ni = 0; ni < 8; ni++) {
                    const int g = ni >> 1, p = (ni & 1) * 2;
                    MMA(acc[mi][ni], af[mi], bf[g][p], bf[g][p + 1]);
                }
        }
        __syncthreads();
    }

    // Epilogue. tq = row-within-8 group, tr selects column pair.
    const int tq = lane >> 2, tr = lane & 3;
    const bool offdiag = (i != j);
    __half* Pb = g_P + (size_t)b * N_TOK * N_TOK;
    __half* T = (__half*)sbase;          // [128 cols][132 rows] staging (transpose)
    float cs[16];
#pragma unroll
    for (int k = 0; k < 16; k++) cs[k] = 0.f;

#pragma unroll
    for (int mi = 0; mi < 2; mi++)
#pragma unroll
        for (int rh = 0; rh < 2; rh++) {
            int r = mbase + mi * 16 + rh * 8 + tq;
            int row = row0 + r;
            float rs = 0.f;
#pragma unroll
            for (int ni = 0; ni < 8; ni++) {
                float e0 = __expf(acc[mi][ni][rh * 2 + 0]);
                float e1 = __expf(acc[mi][ni][rh * 2 + 1]);
                rs += e0 + e1;
                int cc = nbase + ni * 8 + tr * 2;
                __half2 hv = __floats2half2_rn(e0, e1);
                *(uint32_t*)(Pb + (size_t)row * N_TOK + col0 + cc) = *(uint32_t*)&hv;
                if (offdiag) {
                    T[(cc + 0) * 132 + r] = __low2half(hv);
                    T[(cc + 1) * 132 + r] = __high2half(hv);
                    cs[ni * 2 + 0] += e0;
                    cs[ni * 2 + 1] += e1;
                }
            }
            rs += __shfl_xor_sync(0xffffffffu, rs, 1);
            rs += __shfl_xor_sync(0xffffffffu, rs, 2);
            if (tr == 0) atomicAdd(&g_rowsum[b * N_TOK + row], rs);
        }

    if (offdiag) {
        // column sums -> rowsum for the mirrored rows
#pragma unroll
        for (int k = 0; k < 16; k++) {
            cs[k] += __shfl_xor_sync(0xffffffffu, cs[k], 4);
            cs[k] += __shfl_xor_sync(0xffffffffu, cs[k], 8);
            cs[k] += __shfl_xor_sync(0xffffffffu, cs[k], 16);
        }
        if (tq == 0) {
#pragma unroll
            for (int ni = 0; ni < 8; ni++) {
                int cc = nbase + ni * 8 + tr * 2;
                atomicAdd(&g_rowsum[b * N_TOK + col0 + cc + 0], cs[ni * 2 + 0]);
                atomicAdd(&g_rowsum[b * N_TOK + col0 + cc + 1], cs[ni * 2 + 1]);
            }
        }
        __syncthreads();
        // coalesced write of the transposed block
#pragma unroll
        for (int t = 0; t < 32; t++) {
            int q = tid + t * 256;
            int cc = q >> 6, hp = q & 63;
            uint32_t val = *(uint32_t*)&T[cc * 132 + 2 * hp];
            *(uint32_t*)(Pb + (size_t)(col0 + cc) * N_TOK + row0 + 2 * hp) = val;
        }
    }
}

// ---------------------------------------------------------------------------
// Kernel 3: PV. CTA 128x128, out = (P . h^T)/rowsum, single fp16 pass.
// 3-stage cp.async pipeline. Global sumsq.
// ---------------------------------------------------------------------------
__global__ __launch_bounds__(256, 2) void k_pv(float* __restrict__ out) {
    extern __shared__ char smem_raw[];
    uint32_t sb0 = smem_u32(smem_raw);
    uint32_t sb = (sb0 + 1023) & ~1023u;
    char* sbase = smem_raw + (sb - sb0);
    const int tid = threadIdx.x, lane = tid & 31, w = tid >> 5;
    const int b = blockIdx.z, row0 = blockIdx.y * 128, col0 = blockIdx.x * 128;

    const __half* A  = g_P   + ((size_t)b * N_TOK + row0) * N_TOK;
    const __half* Bh = g_hth + ((size_t)b * H_DIM + col0) * N_TOK;

    const int mbase = (w & 3) * 32, nbase = (w >> 2) * 64;
    const uint32_t aRow = a_row_off(mbase, lane);
    const uint32_t bRow = b_row_off(nbase, lane);
    float acc[2][8][4] = {};

    auto load = [&](int c) {
        uint32_t base = sb + (c % 3) * STAGE_BYTES;
        int k0 = c * 64;
#pragma unroll
        for (int t = 0; t < 4; t++) {
            int q = tid + t * 256, r = q >> 3, ch = q & 7;
            uint32_t so = SW((uint32_t)(r * 128 + ch * 16));
            size_t go = (size_t)r * N_TOK + k0 + ch * 8;
            cpa16(base + so,         A + go);
            cpa16(base + 16384 + so, Bh + go);
        }
        CP_COMMIT();
    };

    load(0); load(1);
#pragma unroll 1
    for (int c = 0; c < 32; c++) {
        if (c + 2 < 32)      { load(c + 2); CP_WAIT(2); }
        else if (c + 1 < 32) { CP_WAIT(1); }
        else                 { CP_WAIT(0); }
        __syncthreads();
        uint32_t aB = sb + (c % 3) * STAGE_BYTES, bB = aB + 16384;
#pragma unroll
        for (int k16 = 0; k16 < 4; k16++) {
            uint32_t aoff = SW(aRow + k16 * 32);
            uint32_t boff = SW(bRow + k16 * 32);
            uint32_t af[2][4], bf[4][4];
#pragma unroll
            for (int mi = 0; mi < 2; mi++)
                LDSM4(af[mi][0], af[mi][1], af[mi][2], af[mi][3], aB + aoff + mi * 2048);
#pragma unroll
            for (int g = 0; g < 4; g++)
                LDSM4(bf[g][0], bf[g][1], bf[g][2], bf[g][3], bB + boff + g * 2048);
#pragma unroll
            for (int mi = 0; mi < 2; mi++)
#pragma unroll
                for (int ni = 0; ni < 8; ni++) {
                    const int g = ni >> 1, p = (ni & 1) * 2;
                    MMA(acc[mi][ni], af[mi], bf[g][p], bf[g][p + 1]);
                }
        }
        __syncthreads();
    }

    // Epilogue: scale by 1/rowsum, store, global sumsq.
    const int tq = lane >> 2, tr = lane & 3;
    float ssq = 0.f;
#pragma unroll
    for (int mi = 0; mi < 2; mi++)
#pragma unroll
        for (int rh = 0; rh < 2; rh++) {
            int row = row0 + mbase + mi * 16 + rh * 8 + tq;
            float inv = 1.f / g_rowsum[b * N_TOK + row];
#pragma unroll
            for (int ni = 0; ni < 8; ni++) {
                float v0 = acc[mi][ni][rh * 2 + 0] * inv;
                float v1 = acc[mi][ni][rh * 2 + 1] * inv;
                ssq = fmaf(v0, v0, fmaf(v1, v1, ssq));
                *(float2*)(out + ((size_t)row * B_SZ + b) * H_DIM
                               + col0 + nbase + ni * 8 + tr * 2) = make_float2(v0, v1);
            }
        }
#pragma unroll
    for (int o = 16; o; o >>= 1) ssq += __shfl_xor_sync(0xffffffffu, ssq, o);
    float* red = (float*)sbase;
    __syncthreads();
    if (lane == 0) red[w] = ssq;
    __syncthreads();
    if (tid == 0) {
        float s = 0.f;
#pragma unroll
        for (int i = 0; i < 8; i++) s += red[i];
        atomicAdd(&g_sumsq[0], s);
    }
}

// ---------------------------------------------------------------------------
// Kernel 4: out *= rsqrt(sum(out^2))
// ---------------------------------------------------------------------------
__global__ void k_scale(float* __restrict__ out) {
    float s = rsqrtf(g_sumsq[0]);
    const int total4 = (N_TOK * B_SZ * H_DIM) / 4;
    float4* o4 = (float4*)out;
    for (int i = blockIdx.x * blockDim.x + threadIdx.x; i < total4;
         i += gridDim.x * blockDim.x) {
        float4 v = o4[i];
        v.x *= s; v.y *= s; v.z *= s; v.w *= s;
        o4[i] = v;
    }
}

extern "C" void kernel_launch(void* const* d_in, const int* in_sizes, int n_in,
                              void* d_out, int out_size) {
    (void)in_sizes; (void)n_in; (void)out_size;
    const float* x = (const float*)d_in[0];
    const float* h = (const float*)d_in[1];
    float* out = (float*)d_out;

    cudaFuncSetAttribute(k_qk, cudaFuncAttributeMaxDynamicSharedMemorySize, GEMM_SMEM);
    cudaFuncSetAttribute(k_pv, cudaFuncAttributeMaxDynamicSharedMemorySize, GEMM_SMEM);

    k_normalize<<<(B_SZ * N_TOK) / 8, 256>>>(x);
    k_ht<<<dim3(N_TOK / 32, H_DIM / 32, B_SZ), dim3(32, 8)>>>(h);
    k_qk<<<dim3(136, 1, B_SZ), 256, GEMM_SMEM>>>();
    k_pv<<<dim3(4, 16, B_SZ), 256, GEMM_SMEM>>>(out);
    k_scale<<<1024, 256>>>(out);
}